// round 9
// baseline (speedup 1.0000x reference)
#include <cuda_runtime.h>
#include <math.h>

// ---------------- problem dims ----------------
#define N_TOT 6144
#define NN1   3072           // landmarks
#define NN2   3072           // targets
#define DIN   128
#define DZ    258
#define KP    288            // K padded (zeros) to 9*32
#define DMED  512
#define LCLIP 6.906754778648554f   // log(0.999/0.001)

// ---------------- scratch (static device globals; referenced ONLY from device code) ----------------
__device__ float g_QT[(size_t)N_TOT * KP];        // (comb@Wq + bq)/sqrt(258), padded
__device__ float g_KT[(size_t)N_TOT * KP];        // comb@Wk + bk, padded
__device__ float g_Ablock[(size_t)NN2 * NN1];     // exp(s)*mask on tg->lm block
__device__ float g_AccP[3][(size_t)NN2 * 128];    // K-split partials of adj_block @ lm_X
__device__ float g_DegY[NN2][4];                  // deg+1, y0, y1, pad
__device__ float g_FinalF[(size_t)NN2 * KP];      // [tg_X | f1] padded with zeros
__device__ float g_H[(size_t)NN2 * DMED];

// ---------------- kernel 1: Q/K projection (comb @ W + b), padded to KP cols ----------------
__global__ void __launch_bounds__(256) qk_proj(const float* __restrict__ lmX,
                                               const float* __restrict__ tgX,
                                               const float* __restrict__ W,
                                               const float* __restrict__ bias,
                                               float scale, int which)
{
    __shared__ float Xs[32][128];
    __shared__ float Ws[128][33];
    float* Out = which ? g_KT : g_QT;

    int tid = threadIdx.x;
    int r0 = blockIdx.y * 32;
    int c0 = blockIdx.x * 32;

    for (int idx = tid; idx < 32 * 128; idx += 256) {
        int r = idx >> 7, k = idx & 127;
        int grow = r0 + r;
        const float* src = (grow < NN1) ? (lmX + (size_t)grow * DIN)
                                        : (tgX + (size_t)(grow - NN1) * DIN);
        Xs[r][k] = src[k];
    }
    for (int idx = tid; idx < 128 * 32; idx += 256) {
        int k = idx >> 5, c = idx & 31;
        int col = c0 + c;
        Ws[k][c] = (col < DZ) ? W[(size_t)k * DZ + col] : 0.f;
    }
    __syncthreads();

    int c = tid & 31, rq = tid >> 5;
    float acc[4] = {0.f, 0.f, 0.f, 0.f};
#pragma unroll 4
    for (int k = 0; k < 128; k++) {
        float w = Ws[k][c];
#pragma unroll
        for (int rr = 0; rr < 4; rr++) acc[rr] += Xs[rq * 4 + rr][k] * w;
    }
    int col = c0 + c;
    float b = (col < DZ) ? bias[col] : 0.f;
#pragma unroll
    for (int rr = 0; rr < 4; rr++) {
        float v = (col < DZ) ? (acc[rr] + b) * scale : 0.f;
        Out[(size_t)(r0 + rq * 4 + rr) * KP + col] = v;
    }
}

// ---------------- kernel 2: fused score / prob / mask / adj_block ----------------
// Canonical fp32 SGEMM: 128x128 tile, 256 threads, 8x8 microtile, plain float
// accumulators. Writes g_Ablock DIRECTLY (device symbol, not a host-passed ptr).
__global__ void __launch_bounds__(256) score_kernel(const float* __restrict__ noise,
                                                    float* __restrict__ prob,
                                                    float* __restrict__ mask)
{
    __shared__ float Qs[32][136];   // [k][row], padded pitch
    __shared__ float Ks[32][136];

    int tid = threadIdx.x;
    int tx = tid & 15, ty = tid >> 4;
    int r0 = blockIdx.y * 128;
    int c0 = blockIdx.x * 128;

    float acc[8][8];
#pragma unroll
    for (int i = 0; i < 8; i++)
#pragma unroll
        for (int j = 0; j < 8; j++) acc[i][j] = 0.f;

    for (int kc = 0; kc < 9; kc++) {
        int kb = kc * 32;
#pragma unroll
        for (int it = 0; it < 4; it++) {
            int idx = tid + it * 256;
            int row = idx >> 3;
            int kq = (idx & 7) * 4;
            float4 q = *(const float4*)(g_QT + (size_t)(r0 + row) * KP + kb + kq);
            Qs[kq + 0][row] = q.x;
            Qs[kq + 1][row] = q.y;
            Qs[kq + 2][row] = q.z;
            Qs[kq + 3][row] = q.w;
            float4 kv = *(const float4*)(g_KT + (size_t)(c0 + row) * KP + kb + kq);
            Ks[kq + 0][row] = kv.x;
            Ks[kq + 1][row] = kv.y;
            Ks[kq + 2][row] = kv.z;
            Ks[kq + 3][row] = kv.w;
        }
        __syncthreads();

#pragma unroll 8
        for (int k = 0; k < 32; k++) {
            float a[8], b[8];
#pragma unroll
            for (int i = 0; i < 8; i++) {
                a[i] = Qs[k][ty + 16 * i];
                b[i] = Ks[k][tx + 16 * i];
            }
#pragma unroll
            for (int i = 0; i < 8; i++)
#pragma unroll
                for (int j = 0; j < 8; j++) acc[i][j] += a[i] * b[j];
        }
        __syncthreads();
    }

    bool inblk = (r0 >= NN1) && (c0 < NN1);

#pragma unroll
    for (int i = 0; i < 8; i++) {
        int row = r0 + ty + 16 * i;
        size_t rowoff = (size_t)row * N_TOT;
#pragma unroll
        for (int j = 0; j < 8; j++) {
            int col = c0 + tx + 16 * j;
            float s = acc[i][j];                            // temperature folded into Q
            // mask_a_prob = clip(sigmoid(s), 0.001, 0.999)
            float p = __fdividef(1.f, 1.f + __expf(-s));
            float pc = fminf(fmaxf(p, 0.001f), 0.999f);
            // logits of clipped prob == clamp(s, +-log(999))
            float lg = fminf(fmaxf(s, -LCLIP), LCLIP);
            float u = noise[rowoff + col];
            float logistic = __logf(u) - __logf(1.f - u);   // 1-u exact (Sterbenz) for u>=0.5
            float m = __fdividef(1.f, 1.f + __expf(-(lg + logistic) * 20.f));
            prob[rowoff + col] = pc;
            mask[rowoff + col] = m;
            if (inblk) g_Ablock[(size_t)(row - NN1) * NN1 + col] = __expf(s) * m;
        }
    }
}

// ---------------- kernel 3a: adj_block @ lm_X, K-split-3 register-tiled GEMM ----------------
__global__ void __launch_bounds__(256) adj_gemm(const float* __restrict__ lmX)
{
    __shared__ float As[32][66];
    __shared__ float Bs[32][132];

    int tid = threadIdx.x;
    int tx = tid & 31, ty = tid >> 5;
    int r0 = blockIdx.x * 64;
    int k0 = blockIdx.y * 1024;

    float acc[8][4];
#pragma unroll
    for (int r = 0; r < 8; r++)
#pragma unroll
        for (int c = 0; c < 4; c++) acc[r][c] = 0.f;

    for (int kt = 0; kt < 1024; kt += 32) {
        for (int i = tid; i < 64 * 32; i += 256) {
            int r = i >> 5, kk = i & 31;
            As[kk][r] = g_Ablock[(size_t)(r0 + r) * NN1 + k0 + kt + kk];
        }
        for (int i = tid; i < 32 * 128; i += 256) {
            int kk = i >> 7, c = i & 127;
            Bs[kk][c] = lmX[(size_t)(k0 + kt + kk) * DIN + c];
        }
        __syncthreads();
#pragma unroll
        for (int kk = 0; kk < 32; kk++) {
            float b[4];
            *(float4*)b = *(const float4*)&Bs[kk][tx * 4];
            float a[8];
#pragma unroll
            for (int r = 0; r < 8; r++) a[r] = As[kk][ty * 8 + r];
#pragma unroll
            for (int r = 0; r < 8; r++)
#pragma unroll
                for (int c = 0; c < 4; c++) acc[r][c] += a[r] * b[c];
        }
        __syncthreads();
    }
    float* Out = g_AccP[blockIdx.y];
#pragma unroll
    for (int r = 0; r < 8; r++)
        *(float4*)&Out[(size_t)(r0 + ty * 8 + r) * 128 + tx * 4] = *(const float4*)&acc[r][0];
}

// ---------------- kernel 3b: degree + lm_Y columns (bandwidth bound) ----------------
__global__ void __launch_bounds__(256) adj_small(const float* __restrict__ lmY)
{
    int warp = threadIdx.x >> 5, lane = threadIdx.x & 31;
    int row = blockIdx.x * 8 + warp;
    const float* arow = g_Ablock + (size_t)row * NN1;
    float d = 0.f, y0 = 0.f, y1 = 0.f;
    for (int k = lane; k < NN1; k += 32) {
        float a = arow[k];
        float2 yv = *(const float2*)&lmY[(size_t)k * 2];
        d += a;
        y0 += a * yv.x;
        y1 += a * yv.y;
    }
#pragma unroll
    for (int off = 16; off; off >>= 1) {
        d  += __shfl_down_sync(0xffffffffu, d,  off);
        y0 += __shfl_down_sync(0xffffffffu, y0, off);
        y1 += __shfl_down_sync(0xffffffffu, y1, off);
    }
    if (lane == 0) {
        g_DegY[row][0] = d + 1.0f;
        g_DegY[row][1] = y0;
        g_DegY[row][2] = y1;
    }
}

// ---------------- kernel 4: tg_agg -> w_1 -> FinalF = [tg_X | f1], zero pad ----------------
__global__ void __launch_bounds__(256) finalf_kernel(const float* __restrict__ tgX,
                                                     const float* __restrict__ W1,
                                                     const float* __restrict__ b1)
{
    __shared__ float aggs[16][132];
    int tid = threadIdx.x;
    int r0 = blockIdx.x * 16;

    for (int idx = tid; idx < 16 * 130; idx += 256) {
        int r = idx / 130, cc = idx - r * 130;
        int row = r0 + r;
        float invd = __frcp_rn(g_DegY[row][0]);
        float v;
        if (cc < 128) {
            v = (g_AccP[0][(size_t)row * 128 + cc] + g_AccP[1][(size_t)row * 128 + cc]
               + g_AccP[2][(size_t)row * 128 + cc] + tgX[(size_t)row * DIN + cc]);
        } else {
            v = g_DegY[row][cc - 127];   // cc=128 -> y0, cc=129 -> y1 (tg_feat0 is 0 there)
        }
        aggs[r][cc] = v * invd;
    }
    __syncthreads();

    // copy tg_X into cols [0,128)
    for (int idx = tid; idx < 16 * 128; idx += 256) {
        int r = idx >> 7, cc = idx & 127;
        g_FinalF[(size_t)(r0 + r) * KP + cc] = tgX[(size_t)(r0 + r) * DIN + cc];
    }
    // zero pad cols [258, 288)
    for (int idx = tid; idx < 16 * 30; idx += 256) {
        int r = idx / 30, cc = idx - r * 30;
        g_FinalF[(size_t)(r0 + r) * KP + DZ + cc] = 0.f;
    }
    // f1 = agg @ W1 + b1 into cols [128, 258)
    for (int idx = tid; idx < 16 * 130; idx += 256) {
        int r = idx / 130, cc = idx - r * 130;
        float a = b1[cc];
#pragma unroll 2
        for (int d = 0; d < 130; d++) a += aggs[r][d] * W1[(size_t)d * 130 + cc];
        g_FinalF[(size_t)(r0 + r) * KP + 128 + cc] = a;
    }
}

// ---------------- kernel 5: H = relu(FinalF @ Wp1 + bp1) ----------------
__global__ void __launch_bounds__(256) hgemm_kernel(const float* __restrict__ Wp1,
                                                    const float* __restrict__ bp1)
{
    __shared__ float Fs[32][33];
    __shared__ float Ws[32][33];
    int tid = threadIdx.x;
    int r0 = blockIdx.y * 32;
    int c0 = blockIdx.x * 32;
    int c = tid & 31, rq = tid >> 5;
    float acc[4] = {0.f, 0.f, 0.f, 0.f};

    for (int kb = 0; kb < KP; kb += 32) {
        for (int idx = tid; idx < 32 * 32; idx += 256) {
            int r = idx >> 5, k = idx & 31;
            Fs[r][k] = g_FinalF[(size_t)(r0 + r) * KP + kb + k];
        }
        for (int idx = tid; idx < 32 * 32; idx += 256) {
            int kk = idx >> 5, cc = idx & 31;
            int kg = kb + kk;
            Ws[kk][cc] = (kg < DZ) ? Wp1[(size_t)kg * DMED + c0 + cc] : 0.f;
        }
        __syncthreads();
#pragma unroll
        for (int k = 0; k < 32; k++) {
            float w = Ws[k][c];
#pragma unroll
            for (int rr = 0; rr < 4; rr++) acc[rr] += Fs[rq * 4 + rr][k] * w;
        }
        __syncthreads();
    }
    float b = bp1[c0 + c];
#pragma unroll
    for (int rr = 0; rr < 4; rr++)
        g_H[(size_t)(r0 + rq * 4 + rr) * DMED + c0 + c] = fmaxf(acc[rr] + b, 0.f);
}

// ---------------- kernel 6: y = H @ Wp2 + bp2 ----------------
__global__ void __launch_bounds__(256) yout_kernel(const float* __restrict__ Wp2,
                                                   const float* __restrict__ bp2,
                                                   float* __restrict__ out)
{
    int warp = threadIdx.x >> 5, lane = threadIdx.x & 31;
    int row = blockIdx.x * 8 + warp;
    if (row >= NN2) return;
    const float* h = g_H + (size_t)row * DMED;
    float a0 = 0.f, a1 = 0.f;
    for (int cb = lane; cb < DMED; cb += 32) {
        float hv = h[cb];
        a0 += hv * Wp2[cb * 2 + 0];
        a1 += hv * Wp2[cb * 2 + 1];
    }
#pragma unroll
    for (int off = 16; off; off >>= 1) {
        a0 += __shfl_down_sync(0xffffffffu, a0, off);
        a1 += __shfl_down_sync(0xffffffffu, a1, off);
    }
    if (lane == 0) {
        out[row * 2 + 0] = a0 + bp2[0];
        out[row * 2 + 1] = a1 + bp2[1];
    }
}

// ---------------- launch ----------------
extern "C" void kernel_launch(void* const* d_in, const int* in_sizes, int n_in,
                              void* d_out, int out_size)
{
    const float* lmX  = (const float*)d_in[0];
    const float* lmY  = (const float*)d_in[1];
    const float* tgX  = (const float*)d_in[2];
    // d_in[3] = tg_Y (unused by the reference output)
    const float* Wq   = (const float*)d_in[4];
    const float* bq   = (const float*)d_in[5];
    const float* Wk   = (const float*)d_in[6];
    const float* bk   = (const float*)d_in[7];
    const float* W1   = (const float*)d_in[8];
    const float* b1   = (const float*)d_in[9];
    const float* Wp1  = (const float*)d_in[10];
    const float* bp1  = (const float*)d_in[11];
    const float* Wp2  = (const float*)d_in[12];
    const float* bp2  = (const float*)d_in[13];
    const float* noise = (const float*)d_in[14];
    // d_in[15] = reserve_ratio (== 1, no effect)

    float* out  = (float*)d_out;
    float* y    = out;                                   // [3072, 2]
    float* prob = out + (size_t)NN2 * 2;                 // [6144, 6144]
    float* mask = prob + (size_t)N_TOT * N_TOT;          // [6144, 6144]

    const float invTemp = 1.0f / sqrtf(258.0f);

    qk_proj<<<dim3(KP / 32, N_TOT / 32), 256>>>(lmX, tgX, Wq, bq, invTemp, 0);
    qk_proj<<<dim3(KP / 32, N_TOT / 32), 256>>>(lmX, tgX, Wk, bk, 1.0f, 1);

    score_kernel<<<dim3(N_TOT / 128, N_TOT / 128), 256>>>(noise, prob, mask);

    adj_gemm<<<dim3(NN2 / 64, 3), 256>>>(lmX);
    adj_small<<<NN2 / 8, 256>>>(lmY);
    finalf_kernel<<<NN2 / 16, 256>>>(tgX, W1, b1);
    hgemm_kernel<<<dim3(DMED / 32, NN2 / 32), 256>>>(Wp1, bp1);
    yout_kernel<<<NN2 / 8, 256>>>(Wp2, bp2, y);
}

// round 10
// speedup vs baseline: 1.1153x; 1.1153x over previous
#include <cuda_runtime.h>
#include <math.h>

// ---------------- problem dims ----------------
#define N_TOT 6144
#define NN1   3072           // landmarks
#define NN2   3072           // targets
#define DIN   128
#define DZ    258
#define KP    288            // K padded (zeros) to 9*32
#define DMED  512
#define KSPLIT 6
#define LCLIP 6.906754778648554f   // log(0.999/0.001)

typedef unsigned long long u64;

// ---------------- scratch (static device globals; referenced ONLY from device code) ----------------
__device__ float g_QT[(size_t)N_TOT * KP];        // (comb@Wq + bq)/sqrt(258), padded
__device__ float g_KT[(size_t)N_TOT * KP];        // comb@Wk + bk, padded
__device__ float g_Ablock[(size_t)NN2 * NN1];     // exp(s)*mask on tg->lm block
__device__ float g_AccP[KSPLIT][(size_t)NN2 * 128]; // K-split partials of adj_block @ lm_X
__device__ float g_DegY[NN2][4];                  // deg+1, y0, y1, pad
__device__ float g_FinalF[(size_t)NN2 * KP];      // [tg_X | f1] padded with zeros
__device__ float g_H[(size_t)NN2 * DMED];

// ---------------- helpers ----------------
__device__ __forceinline__ u64 ffma2(u64 a, u64 b, u64 c) {
    u64 d;
    asm("fma.rn.f32x2 %0, %1, %2, %3;" : "=l"(d) : "l"(a), "l"(b), "l"(c));
    return d;
}
__device__ __forceinline__ u64 dup2(float v) {
    u64 d;
    unsigned r = __float_as_uint(v);
    asm("mov.b64 %0, {%1, %1};" : "=l"(d) : "r"(r));
    return d;
}
__device__ __forceinline__ float lo32(u64 v) { return __uint_as_float((unsigned)(v & 0xffffffffull)); }
__device__ __forceinline__ float hi32(u64 v) { return __uint_as_float((unsigned)(v >> 32)); }

// ---------------- kernel 1: Q/K projection (comb @ W + b), padded to KP cols ----------------
__global__ void __launch_bounds__(256) qk_proj(const float* __restrict__ lmX,
                                               const float* __restrict__ tgX,
                                               const float* __restrict__ W,
                                               const float* __restrict__ bias,
                                               float scale, int which)
{
    __shared__ float Xs[32][128];
    __shared__ float Ws[128][33];
    float* Out = which ? g_KT : g_QT;

    int tid = threadIdx.x;
    int r0 = blockIdx.y * 32;
    int c0 = blockIdx.x * 32;

    for (int idx = tid; idx < 32 * 128; idx += 256) {
        int r = idx >> 7, k = idx & 127;
        int grow = r0 + r;
        const float* src = (grow < NN1) ? (lmX + (size_t)grow * DIN)
                                        : (tgX + (size_t)(grow - NN1) * DIN);
        Xs[r][k] = src[k];
    }
    for (int idx = tid; idx < 128 * 32; idx += 256) {
        int k = idx >> 5, c = idx & 31;
        int col = c0 + c;
        Ws[k][c] = (col < DZ) ? W[(size_t)k * DZ + col] : 0.f;
    }
    __syncthreads();

    int c = tid & 31, rq = tid >> 5;
    float acc[4] = {0.f, 0.f, 0.f, 0.f};
#pragma unroll 4
    for (int k = 0; k < 128; k++) {
        float w = Ws[k][c];
#pragma unroll
        for (int rr = 0; rr < 4; rr++) acc[rr] += Xs[rq * 4 + rr][k] * w;
    }
    int col = c0 + c;
    float b = (col < DZ) ? bias[col] : 0.f;
#pragma unroll
    for (int rr = 0; rr < 4; rr++) {
        float v = (col < DZ) ? (acc[rr] + b) * scale : 0.f;
        Out[(size_t)(r0 + rq * 4 + rr) * KP + col] = v;
    }
}

// ---------------- kernel 2: fused score / prob / mask / adj_block ----------------
// 128x128 tile, 256 threads, 8x8 microtile. Row-paired f32x2 accumulators:
// acc[4][8] u64 (64 regs), rows ty*8..ty*8+7 adjacent -> a loads are LDS.64,
// only b scalars need a 1-instr dup. Halves FFMA issue count vs scalar fp32.
__global__ void __launch_bounds__(256) score_kernel(const float* __restrict__ noise,
                                                    float* __restrict__ prob,
                                                    float* __restrict__ mask)
{
    __shared__ float Qs[32][136];   // [k][row], padded pitch (544B, 8B-aligned rows)
    __shared__ float Ks[32][136];

    int tid = threadIdx.x;
    int tx = tid & 15, ty = tid >> 4;
    int r0 = blockIdx.y * 128;
    int c0 = blockIdx.x * 128;

    u64 acc[4][8];
#pragma unroll
    for (int i = 0; i < 4; i++)
#pragma unroll
        for (int j = 0; j < 8; j++) acc[i][j] = 0ull;

    for (int kc = 0; kc < 9; kc++) {
        int kb = kc * 32;
#pragma unroll
        for (int it = 0; it < 4; it++) {
            int idx = tid + it * 256;
            int row = idx >> 3;
            int kq = (idx & 7) * 4;
            float4 q = *(const float4*)(g_QT + (size_t)(r0 + row) * KP + kb + kq);
            Qs[kq + 0][row] = q.x;
            Qs[kq + 1][row] = q.y;
            Qs[kq + 2][row] = q.z;
            Qs[kq + 3][row] = q.w;
            float4 kv = *(const float4*)(g_KT + (size_t)(c0 + row) * KP + kb + kq);
            Ks[kq + 0][row] = kv.x;
            Ks[kq + 1][row] = kv.y;
            Ks[kq + 2][row] = kv.z;
            Ks[kq + 3][row] = kv.w;
        }
        __syncthreads();

#pragma unroll 4
        for (int k = 0; k < 32; k++) {
            u64 a[4];
            u64 bd[8];
#pragma unroll
            for (int i = 0; i < 4; i++)
                a[i] = *(const u64*)&Qs[k][ty * 8 + 2 * i];     // rows pair (2i, 2i+1)
#pragma unroll
            for (int j = 0; j < 8; j++)
                bd[j] = dup2(Ks[k][tx + 16 * j]);
#pragma unroll
            for (int i = 0; i < 4; i++)
#pragma unroll
                for (int j = 0; j < 8; j++) acc[i][j] = ffma2(a[i], bd[j], acc[i][j]);
        }
        __syncthreads();
    }

    bool inblk = (r0 >= NN1) && (c0 < NN1);

#pragma unroll
    for (int i = 0; i < 4; i++) {
#pragma unroll
        for (int h = 0; h < 2; h++) {
            int row = r0 + ty * 8 + 2 * i + h;
            size_t rowoff = (size_t)row * N_TOT;
#pragma unroll
            for (int j = 0; j < 8; j++) {
                int col = c0 + tx + 16 * j;
                float s = h ? hi32(acc[i][j]) : lo32(acc[i][j]);  // temperature folded into Q
                // mask_a_prob = clip(sigmoid(s), 0.001, 0.999)
                float p = __fdividef(1.f, 1.f + __expf(-s));
                float pc = fminf(fmaxf(p, 0.001f), 0.999f);
                // logits of clipped prob == clamp(s, +-log(999))
                float lg = fminf(fmaxf(s, -LCLIP), LCLIP);
                float u = __ldcs(noise + rowoff + col);
                float logistic = __logf(u) - __logf(1.f - u);     // 1-u exact (Sterbenz) for u>=0.5
                float m = __fdividef(1.f, 1.f + __expf(-(lg + logistic) * 20.f));
                __stcs(prob + rowoff + col, pc);
                __stcs(mask + rowoff + col, m);
                if (inblk) g_Ablock[(size_t)(row - NN1) * NN1 + col] = __expf(s) * m;
            }
        }
    }
}

// ---------------- kernel 3a: adj_block @ lm_X, K-split-6 register-tiled GEMM ----------------
// grid (NN2/64, KSPLIT) = 288 CTAs -> ~2 per SM (was 144 -> grid-starved).
__global__ void __launch_bounds__(256) adj_gemm(const float* __restrict__ lmX)
{
    __shared__ float As[32][66];
    __shared__ float Bs[32][132];

    int tid = threadIdx.x;
    int tx = tid & 31, ty = tid >> 5;
    int r0 = blockIdx.x * 64;
    int k0 = blockIdx.y * (NN1 / KSPLIT);

    float acc[8][4];
#pragma unroll
    for (int r = 0; r < 8; r++)
#pragma unroll
        for (int c = 0; c < 4; c++) acc[r][c] = 0.f;

    for (int kt = 0; kt < NN1 / KSPLIT; kt += 32) {
        for (int i = tid; i < 64 * 32; i += 256) {
            int r = i >> 5, kk = i & 31;
            As[kk][r] = g_Ablock[(size_t)(r0 + r) * NN1 + k0 + kt + kk];
        }
        for (int i = tid; i < 32 * 128; i += 256) {
            int kk = i >> 7, c = i & 127;
            Bs[kk][c] = lmX[(size_t)(k0 + kt + kk) * DIN + c];
        }
        __syncthreads();
#pragma unroll
        for (int kk = 0; kk < 32; kk++) {
            float b[4];
            *(float4*)b = *(const float4*)&Bs[kk][tx * 4];
            float a[8];
#pragma unroll
            for (int r = 0; r < 8; r++) a[r] = As[kk][ty * 8 + r];
#pragma unroll
            for (int r = 0; r < 8; r++)
#pragma unroll
                for (int c = 0; c < 4; c++) acc[r][c] += a[r] * b[c];
        }
        __syncthreads();
    }
    float* Out = g_AccP[blockIdx.y];
#pragma unroll
    for (int r = 0; r < 8; r++)
        *(float4*)&Out[(size_t)(r0 + ty * 8 + r) * 128 + tx * 4] = *(const float4*)&acc[r][0];
}

// ---------------- kernel 3b: degree + lm_Y columns (bandwidth bound) ----------------
__global__ void __launch_bounds__(256) adj_small(const float* __restrict__ lmY)
{
    int warp = threadIdx.x >> 5, lane = threadIdx.x & 31;
    int row = blockIdx.x * 8 + warp;
    const float* arow = g_Ablock + (size_t)row * NN1;
    float d = 0.f, y0 = 0.f, y1 = 0.f;
    for (int k = lane; k < NN1; k += 32) {
        float a = arow[k];
        float2 yv = *(const float2*)&lmY[(size_t)k * 2];
        d += a;
        y0 += a * yv.x;
        y1 += a * yv.y;
    }
#pragma unroll
    for (int off = 16; off; off >>= 1) {
        d  += __shfl_down_sync(0xffffffffu, d,  off);
        y0 += __shfl_down_sync(0xffffffffu, y0, off);
        y1 += __shfl_down_sync(0xffffffffu, y1, off);
    }
    if (lane == 0) {
        g_DegY[row][0] = d + 1.0f;
        g_DegY[row][1] = y0;
        g_DegY[row][2] = y1;
    }
}

// ---------------- kernel 4: tg_agg -> w_1 -> FinalF = [tg_X | f1], zero pad ----------------
__global__ void __launch_bounds__(256) finalf_kernel(const float* __restrict__ tgX,
                                                     const float* __restrict__ W1,
                                                     const float* __restrict__ b1)
{
    __shared__ float aggs[16][132];
    int tid = threadIdx.x;
    int r0 = blockIdx.x * 16;

    for (int idx = tid; idx < 16 * 130; idx += 256) {
        int r = idx / 130, cc = idx - r * 130;
        int row = r0 + r;
        float invd = __frcp_rn(g_DegY[row][0]);
        float v;
        if (cc < 128) {
            v = tgX[(size_t)row * DIN + cc];
#pragma unroll
            for (int p = 0; p < KSPLIT; p++) v += g_AccP[p][(size_t)row * 128 + cc];
        } else {
            v = g_DegY[row][cc - 127];   // cc=128 -> y0, cc=129 -> y1 (tg_feat0 is 0 there)
        }
        aggs[r][cc] = v * invd;
    }
    __syncthreads();

    // copy tg_X into cols [0,128)
    for (int idx = tid; idx < 16 * 128; idx += 256) {
        int r = idx >> 7, cc = idx & 127;
        g_FinalF[(size_t)(r0 + r) * KP + cc] = tgX[(size_t)(r0 + r) * DIN + cc];
    }
    // zero pad cols [258, 288)
    for (int idx = tid; idx < 16 * 30; idx += 256) {
        int r = idx / 30, cc = idx - r * 30;
        g_FinalF[(size_t)(r0 + r) * KP + DZ + cc] = 0.f;
    }
    // f1 = agg @ W1 + b1 into cols [128, 258)
    for (int idx = tid; idx < 16 * 130; idx += 256) {
        int r = idx / 130, cc = idx - r * 130;
        float a = b1[cc];
#pragma unroll 2
        for (int d = 0; d < 130; d++) a += aggs[r][d] * W1[(size_t)d * 130 + cc];
        g_FinalF[(size_t)(r0 + r) * KP + 128 + cc] = a;
    }
}

// ---------------- kernel 5: H = relu(FinalF @ Wp1 + bp1) ----------------
__global__ void __launch_bounds__(256) hgemm_kernel(const float* __restrict__ Wp1,
                                                    const float* __restrict__ bp1)
{
    __shared__ float Fs[32][33];
    __shared__ float Ws[32][33];
    int tid = threadIdx.x;
    int r0 = blockIdx.y * 32;
    int c0 = blockIdx.x * 32;
    int c = tid & 31, rq = tid >> 5;
    float acc[4] = {0.f, 0.f, 0.f, 0.f};

    for (int kb = 0; kb < KP; kb += 32) {
        for (int idx = tid; idx < 32 * 32; idx += 256) {
            int r = idx >> 5, k = idx & 31;
            Fs[r][k] = g_FinalF[(size_t)(r0 + r) * KP + kb + k];
        }
        for (int idx = tid; idx < 32 * 32; idx += 256) {
            int kk = idx >> 5, cc = idx & 31;
            int kg = kb + kk;
            Ws[kk][cc] = (kg < DZ) ? Wp1[(size_t)kg * DMED + c0 + cc] : 0.f;
        }
        __syncthreads();
#pragma unroll
        for (int k = 0; k < 32; k++) {
            float w = Ws[k][c];
#pragma unroll
            for (int rr = 0; rr < 4; rr++) acc[rr] += Fs[rq * 4 + rr][k] * w;
        }
        __syncthreads();
    }
    float b = bp1[c0 + c];
#pragma unroll
    for (int rr = 0; rr < 4; rr++)
        g_H[(size_t)(r0 + rq * 4 + rr) * DMED + c0 + c] = fmaxf(acc[rr] + b, 0.f);
}

// ---------------- kernel 6: y = H @ Wp2 + bp2 ----------------
__global__ void __launch_bounds__(256) yout_kernel(const float* __restrict__ Wp2,
                                                   const float* __restrict__ bp2,
                                                   float* __restrict__ out)
{
    int warp = threadIdx.x >> 5, lane = threadIdx.x & 31;
    int row = blockIdx.x * 8 + warp;
    if (row >= NN2) return;
    const float* h = g_H + (size_t)row * DMED;
    float a0 = 0.f, a1 = 0.f;
    for (int cb = lane; cb < DMED; cb += 32) {
        float hv = h[cb];
        a0 += hv * Wp2[cb * 2 + 0];
        a1 += hv * Wp2[cb * 2 + 1];
    }
#pragma unroll
    for (int off = 16; off; off >>= 1) {
        a0 += __shfl_down_sync(0xffffffffu, a0, off);
        a1 += __shfl_down_sync(0xffffffffu, a1, off);
    }
    if (lane == 0) {
        out[row * 2 + 0] = a0 + bp2[0];
        out[row * 2 + 1] = a1 + bp2[1];
    }
}

// ---------------- launch ----------------
extern "C" void kernel_launch(void* const* d_in, const int* in_sizes, int n_in,
                              void* d_out, int out_size)
{
    const float* lmX  = (const float*)d_in[0];
    const float* lmY  = (const float*)d_in[1];
    const float* tgX  = (const float*)d_in[2];
    // d_in[3] = tg_Y (unused by the reference output)
    const float* Wq   = (const float*)d_in[4];
    const float* bq   = (const float*)d_in[5];
    const float* Wk   = (const float*)d_in[6];
    const float* bk   = (const float*)d_in[7];
    const float* W1   = (const float*)d_in[8];
    const float* b1   = (const float*)d_in[9];
    const float* Wp1  = (const float*)d_in[10];
    const float* bp1  = (const float*)d_in[11];
    const float* Wp2  = (const float*)d_in[12];
    const float* bp2  = (const float*)d_in[13];
    const float* noise = (const float*)d_in[14];
    // d_in[15] = reserve_ratio (== 1, no effect)

    float* out  = (float*)d_out;
    float* y    = out;                                   // [3072, 2]
    float* prob = out + (size_t)NN2 * 2;                 // [6144, 6144]
    float* mask = prob + (size_t)N_TOT * N_TOT;          // [6144, 6144]

    const float invTemp = 1.0f / sqrtf(258.0f);

    qk_proj<<<dim3(KP / 32, N_TOT / 32), 256>>>(lmX, tgX, Wq, bq, invTemp, 0);
    qk_proj<<<dim3(KP / 32, N_TOT / 32), 256>>>(lmX, tgX, Wk, bk, 1.0f, 1);

    score_kernel<<<dim3(N_TOT / 128, N_TOT / 128), 256>>>(noise, prob, mask);

    adj_gemm<<<dim3(NN2 / 64, KSPLIT), 256>>>(lmX);
    adj_small<<<NN2 / 8, 256>>>(lmY);
    finalf_kernel<<<NN2 / 16, 256>>>(tgX, W1, b1);
    hgemm_kernel<<<dim3(DMED / 32, NN2 / 32), 256>>>(Wp1, bp1);
    yout_kernel<<<NN2 / 8, 256>>>(Wp2, bp2, y);
}

// round 14
// speedup vs baseline: 1.6651x; 1.4930x over previous
#include <cuda_runtime.h>
#include <cuda_bf16.h>
#include <math.h>

// ---------------- problem dims ----------------
#define N_TOT 6144
#define NN1   3072           // landmarks
#define NN2   3072           // targets
#define DIN   128
#define DZ    258
#define KP    288            // K padding (9 chunks of 32), both fp32 tail path and bf16 score path
#define DMED  512
#define KSPLIT 6
#define LCLIP 6.906754778648554f   // log(0.999/0.001)

typedef unsigned long long u64;
typedef unsigned int u32;

// ---------------- scratch (static device globals; referenced ONLY from device code) ----------------
__device__ __nv_bfloat16 g_Qhi[(size_t)N_TOT * KP];   // bf16 hi of (comb@Wq+bq)/sqrt(258)
__device__ __nv_bfloat16 g_Qlo[(size_t)N_TOT * KP];   // bf16 lo remainder
__device__ __nv_bfloat16 g_Khi[(size_t)N_TOT * KP];
__device__ __nv_bfloat16 g_Klo[(size_t)N_TOT * KP];
__device__ float g_Ablock[(size_t)NN2 * NN1];         // exp(s)*mask on tg->lm block
__device__ float g_AccP[KSPLIT][(size_t)NN2 * 128];   // K-split partials of adj_block @ lm_X
__device__ float g_DegY[NN2][4];                      // deg+1, y0, y1, pad
__device__ float g_FinalF[(size_t)NN2 * KP];          // [tg_X | f1] padded with zeros
__device__ float g_H[(size_t)NN2 * DMED];

// ---------------- mma.sync helpers (portable sm_80+ PTX) ----------------
__device__ __forceinline__ void ldsm_x4(u32* r, u32 addr) {
    asm volatile("ldmatrix.sync.aligned.m8n8.x4.shared.b16 {%0,%1,%2,%3}, [%4];"
                 : "=r"(r[0]), "=r"(r[1]), "=r"(r[2]), "=r"(r[3]) : "r"(addr));
}
__device__ __forceinline__ void mma_bf16(float* c, const u32* a, const u32* b) {
    asm volatile(
        "mma.sync.aligned.m16n8k16.row.col.f32.bf16.bf16.f32 "
        "{%0,%1,%2,%3}, {%4,%5,%6,%7}, {%8,%9}, {%0,%1,%2,%3};"
        : "+f"(c[0]), "+f"(c[1]), "+f"(c[2]), "+f"(c[3])
        : "r"(a[0]), "r"(a[1]), "r"(a[2]), "r"(a[3]), "r"(b[0]), "r"(b[1]));
}

// ---------------- kernel 1: Q/K projection -> bf16 hi/lo row-major, K padded to 288 ----------------
// grid (KP/32=9, N_TOT/32=192). which==0: Q (scaled by invTemp), which==1: K.
__global__ void __launch_bounds__(256) qk_proj(const float* __restrict__ lmX,
                                               const float* __restrict__ tgX,
                                               const float* __restrict__ W,
                                               const float* __restrict__ bias,
                                               float scale, int which)
{
    __shared__ float Xs[32][128];
    __shared__ float Ws[128][33];

    int tid = threadIdx.x;
    int r0 = blockIdx.y * 32;
    int c0 = blockIdx.x * 32;

    for (int idx = tid; idx < 32 * 128; idx += 256) {
        int r = idx >> 7, k = idx & 127;
        int grow = r0 + r;
        const float* src = (grow < NN1) ? (lmX + (size_t)grow * DIN)
                                        : (tgX + (size_t)(grow - NN1) * DIN);
        Xs[r][k] = src[k];
    }
    for (int idx = tid; idx < 128 * 32; idx += 256) {
        int k = idx >> 5, c = idx & 31;
        int col = c0 + c;
        Ws[k][c] = (col < DZ) ? W[(size_t)k * DZ + col] : 0.f;
    }
    __syncthreads();

    int c = tid & 31, rq = tid >> 5;
    float acc[4] = {0.f, 0.f, 0.f, 0.f};
#pragma unroll 4
    for (int k = 0; k < 128; k++) {
        float w = Ws[k][c];
#pragma unroll
        for (int rr = 0; rr < 4; rr++) acc[rr] += Xs[rq * 4 + rr][k] * w;
    }
    int col = c0 + c;
    float b = (col < DZ) ? bias[col] : 0.f;
    __nv_bfloat16* Ohi = which ? g_Khi : g_Qhi;
    __nv_bfloat16* Olo = which ? g_Klo : g_Qlo;
#pragma unroll
    for (int rr = 0; rr < 4; rr++) {
        int grow = r0 + rq * 4 + rr;
        float v = (col < DZ) ? (acc[rr] + b) * scale : 0.f;
        __nv_bfloat16 hi = __float2bfloat16(v);
        __nv_bfloat16 lo = __float2bfloat16(v - __bfloat162float(hi));
        Ohi[(size_t)grow * KP + col] = hi;
        Olo[(size_t)grow * KP + col] = lo;
    }
}

// ---------------- kernel 2: tensor-core score via mma.sync + fused epilogue ----------------
// 128x128 tile per CTA; 8 warps in 2(M)x4(N); warp tile 64x32; bf16 3-pass split.
__global__ void __launch_bounds__(256) score_mma(const float* __restrict__ noise,
                                                 float* __restrict__ prob,
                                                 float* __restrict__ mask)
{
    __shared__ __nv_bfloat16 Ah[128][40];   // Q hi, rows=m, 40-pitch (80B, conflict-free ldsm)
    __shared__ __nv_bfloat16 Al[128][40];   // Q lo
    __shared__ __nv_bfloat16 Bh[128][40];   // K hi, rows=n
    __shared__ __nv_bfloat16 Bl[128][40];   // K lo

    int tid = threadIdx.x;
    int wid = tid >> 5, lane = tid & 31;
    int wm = wid & 1, wn = wid >> 1;         // warp grid 2(M) x 4(N)
    int r0 = blockIdx.y * 128;
    int c0 = blockIdx.x * 128;

    float c[4][4][4];                         // [mt][nt][frag], 64 regs
#pragma unroll
    for (int mt = 0; mt < 4; mt++)
#pragma unroll
        for (int nt = 0; nt < 4; nt++)
#pragma unroll
            for (int q = 0; q < 4; q++) c[mt][nt][q] = 0.f;

    // precomputed ldmatrix smem addresses (depend only on lane)
    int a_row = wm * 64 + (lane & 15);
    int a_col = (lane >> 4) * 8;
    int b_row = wn * 32 + (lane & 7) + ((lane >> 4) & 1) * 8;
    int b_col = ((lane >> 3) & 1) * 8;

    for (int chunk = 0; chunk < 9; chunk++) {
        int kb = chunk * 32;
        for (int i = tid; i < 512; i += 256) {
            int row = i >> 2;
            int kq = (i & 3) * 8;
            *(float4*)&Ah[row][kq] = *(const float4*)&g_Qhi[(size_t)(r0 + row) * KP + kb + kq];
            *(float4*)&Al[row][kq] = *(const float4*)&g_Qlo[(size_t)(r0 + row) * KP + kb + kq];
            *(float4*)&Bh[row][kq] = *(const float4*)&g_Khi[(size_t)(c0 + row) * KP + kb + kq];
            *(float4*)&Bl[row][kq] = *(const float4*)&g_Klo[(size_t)(c0 + row) * KP + kb + kq];
        }
        __syncthreads();

#pragma unroll
        for (int ks = 0; ks < 2; ks++) {
            int k16 = ks * 16;
            u32 ah[4][4], al[4][4];
#pragma unroll
            for (int mt = 0; mt < 4; mt++) {
                u32 aaddr = (u32)__cvta_generic_to_shared(&Ah[a_row + mt * 16][k16 + a_col]);
                ldsm_x4(ah[mt], aaddr);
                u32 aaddr2 = (u32)__cvta_generic_to_shared(&Al[a_row + mt * 16][k16 + a_col]);
                ldsm_x4(al[mt], aaddr2);
            }
            u32 bh[2][4], bl[2][4];
#pragma unroll
            for (int bt = 0; bt < 2; bt++) {
                u32 baddr = (u32)__cvta_generic_to_shared(&Bh[b_row + bt * 16][k16 + b_col]);
                ldsm_x4(bh[bt], baddr);
                u32 baddr2 = (u32)__cvta_generic_to_shared(&Bl[b_row + bt * 16][k16 + b_col]);
                ldsm_x4(bl[bt], baddr2);
            }
#pragma unroll
            for (int mt = 0; mt < 4; mt++)
#pragma unroll
                for (int bt = 0; bt < 2; bt++)
#pragma unroll
                    for (int h = 0; h < 2; h++) {
                        int nt = bt * 2 + h;
                        mma_bf16(c[mt][nt], ah[mt], &bh[bt][h * 2]);   // hi*hi
                        mma_bf16(c[mt][nt], ah[mt], &bl[bt][h * 2]);   // hi*lo
                        mma_bf16(c[mt][nt], al[mt], &bh[bt][h * 2]);   // lo*hi
                    }
        }
        __syncthreads();
    }

    // epilogue: thread (g = lane>>2, tg = lane&3)
    int g = lane >> 2, tg = lane & 3;
    bool inblk = (r0 >= NN1) && (c0 < NN1);

#pragma unroll
    for (int mt = 0; mt < 4; mt++) {
#pragma unroll
        for (int h = 0; h < 2; h++) {
            int row = r0 + wm * 64 + mt * 16 + g + h * 8;
            size_t rowoff = (size_t)row * N_TOT;
#pragma unroll
            for (int nt = 0; nt < 4; nt++) {
                int col = c0 + wn * 32 + nt * 8 + tg * 2;
                float u0 = __ldcs(noise + rowoff + col);
                float u1 = __ldcs(noise + rowoff + col + 1);
                float pcv[2], mv[2], av[2];
#pragma unroll
                for (int q = 0; q < 2; q++) {
                    float s = c[mt][nt][h * 2 + q];
                    float p = __fdividef(1.f, 1.f + __expf(-s));
                    pcv[q] = fminf(fmaxf(p, 0.001f), 0.999f);
                    float lg = fminf(fmaxf(s, -LCLIP), LCLIP);
                    float u = q ? u1 : u0;
                    float logistic = __logf(u) - __logf(1.f - u);
                    mv[q] = __fdividef(1.f, 1.f + __expf(-(lg + logistic) * 20.f));
                    av[q] = __expf(s) * mv[q];
                }
                __stcs((float2*)(prob + rowoff + col), make_float2(pcv[0], pcv[1]));
                __stcs((float2*)(mask + rowoff + col), make_float2(mv[0], mv[1]));
                if (inblk)
                    *(float2*)(g_Ablock + (size_t)(row - NN1) * NN1 + col) = make_float2(av[0], av[1]);
            }
        }
    }
}

// ---------------- kernel 3a: adj_block @ lm_X, K-split-6 register-tiled GEMM ----------------
__global__ void __launch_bounds__(256) adj_gemm(const float* __restrict__ lmX)
{
    __shared__ float As[32][66];
    __shared__ float Bs[32][132];

    int tid = threadIdx.x;
    int tx = tid & 31, ty = tid >> 5;
    int r0 = blockIdx.x * 64;
    int k0 = blockIdx.y * (NN1 / KSPLIT);

    float acc[8][4];
#pragma unroll
    for (int r = 0; r < 8; r++)
#pragma unroll
        for (int c = 0; c < 4; c++) acc[r][c] = 0.f;

    for (int kt = 0; kt < NN1 / KSPLIT; kt += 32) {
        for (int i = tid; i < 64 * 32; i += 256) {
            int r = i >> 5, kk = i & 31;
            As[kk][r] = g_Ablock[(size_t)(r0 + r) * NN1 + k0 + kt + kk];
        }
        for (int i = tid; i < 32 * 128; i += 256) {
            int kk = i >> 7, c = i & 127;
            Bs[kk][c] = lmX[(size_t)(k0 + kt + kk) * DIN + c];
        }
        __syncthreads();
#pragma unroll
        for (int kk = 0; kk < 32; kk++) {
            float b[4];
            *(float4*)b = *(const float4*)&Bs[kk][tx * 4];
            float a[8];
#pragma unroll
            for (int r = 0; r < 8; r++) a[r] = As[kk][ty * 8 + r];
#pragma unroll
            for (int r = 0; r < 8; r++)
#pragma unroll
                for (int c = 0; c < 4; c++) acc[r][c] += a[r] * b[c];
        }
        __syncthreads();
    }
    float* Out = g_AccP[blockIdx.y];
#pragma unroll
    for (int r = 0; r < 8; r++)
        *(float4*)&Out[(size_t)(r0 + ty * 8 + r) * 128 + tx * 4] = *(const float4*)&acc[r][0];
}

// ---------------- kernel 3b: degree + lm_Y columns (bandwidth bound) ----------------
__global__ void __launch_bounds__(256) adj_small(const float* __restrict__ lmY)
{
    int warp = threadIdx.x >> 5, lane = threadIdx.x & 31;
    int row = blockIdx.x * 8 + warp;
    const float* arow = g_Ablock + (size_t)row * NN1;
    float d = 0.f, y0 = 0.f, y1 = 0.f;
    for (int k = lane; k < NN1; k += 32) {
        float a = arow[k];
        float2 yv = *(const float2*)&lmY[(size_t)k * 2];
        d += a;
        y0 += a * yv.x;
        y1 += a * yv.y;
    }
#pragma unroll
    for (int off = 16; off; off >>= 1) {
        d  += __shfl_down_sync(0xffffffffu, d,  off);
        y0 += __shfl_down_sync(0xffffffffu, y0, off);
        y1 += __shfl_down_sync(0xffffffffu, y1, off);
    }
    if (lane == 0) {
        g_DegY[row][0] = d + 1.0f;
        g_DegY[row][1] = y0;
        g_DegY[row][2] = y1;
    }
}

// ---------------- kernel 4: tg_agg -> w_1 -> FinalF = [tg_X | f1], zero pad ----------------
__global__ void __launch_bounds__(256) finalf_kernel(const float* __restrict__ tgX,
                                                     const float* __restrict__ W1,
                                                     const float* __restrict__ b1)
{
    __shared__ float aggs[16][132];
    int tid = threadIdx.x;
    int r0 = blockIdx.x * 16;

    for (int idx = tid; idx < 16 * 130; idx += 256) {
        int r = idx / 130, cc = idx - r * 130;
        int row = r0 + r;
        float invd = __frcp_rn(g_DegY[row][0]);
        float v;
        if (cc < 128) {
            v = tgX[(size_t)row * DIN + cc];
#pragma unroll
            for (int p = 0; p < KSPLIT; p++) v += g_AccP[p][(size_t)row * 128 + cc];
        } else {
            v = g_DegY[row][cc - 127];   // cc=128 -> y0, cc=129 -> y1 (tg_feat0 is 0 there)
        }
        aggs[r][cc] = v * invd;
    }
    __syncthreads();

    for (int idx = tid; idx < 16 * 128; idx += 256) {
        int r = idx >> 7, cc = idx & 127;
        g_FinalF[(size_t)(r0 + r) * KP + cc] = tgX[(size_t)(r0 + r) * DIN + cc];
    }
    for (int idx = tid; idx < 16 * 30; idx += 256) {
        int r = idx / 30, cc = idx - r * 30;
        g_FinalF[(size_t)(r0 + r) * KP + DZ + cc] = 0.f;
    }
    for (int idx = tid; idx < 16 * 130; idx += 256) {
        int r = idx / 130, cc = idx - r * 130;
        float a = b1[cc];
#pragma unroll 2
        for (int d = 0; d < 130; d++) a += aggs[r][d] * W1[(size_t)d * 130 + cc];
        g_FinalF[(size_t)(r0 + r) * KP + 128 + cc] = a;
    }
}

// ---------------- kernel 5: H = relu(FinalF @ Wp1 + bp1) ----------------
__global__ void __launch_bounds__(256) hgemm_kernel(const float* __restrict__ Wp1,
                                                    const float* __restrict__ bp1)
{
    __shared__ float Fs[32][33];
    __shared__ float Ws[32][33];
    int tid = threadIdx.x;
    int r0 = blockIdx.y * 32;
    int c0 = blockIdx.x * 32;
    int c = tid & 31, rq = tid >> 5;
    float acc[4] = {0.f, 0.f, 0.f, 0.f};

    for (int kb = 0; kb < KP; kb += 32) {
        for (int idx = tid; idx < 32 * 32; idx += 256) {
            int r = idx >> 5, k = idx & 31;
            Fs[r][k] = g_FinalF[(size_t)(r0 + r) * KP + kb + k];
        }
        for (int idx = tid; idx < 32 * 32; idx += 256) {
            int kk = idx >> 5, cc = idx & 31;
            int kg = kb + kk;
            Ws[kk][cc] = (kg < DZ) ? Wp1[(size_t)kg * DMED + c0 + cc] : 0.f;
        }
        __syncthreads();
#pragma unroll
        for (int k = 0; k < 32; k++) {
            float w = Ws[k][c];
#pragma unroll
            for (int rr = 0; rr < 4; rr++) acc[rr] += Fs[rq * 4 + rr][k] * w;
        }
        __syncthreads();
    }
    float b = bp1[c0 + c];
#pragma unroll
    for (int rr = 0; rr < 4; rr++)
        g_H[(size_t)(r0 + rq * 4 + rr) * DMED + c0 + c] = fmaxf(acc[rr] + b, 0.f);
}

// ---------------- kernel 6: y = H @ Wp2 + bp2 ----------------
__global__ void __launch_bounds__(256) yout_kernel(const float* __restrict__ Wp2,
                                                   const float* __restrict__ bp2,
                                                   float* __restrict__ out)
{
    int warp = threadIdx.x >> 5, lane = threadIdx.x & 31;
    int row = blockIdx.x * 8 + warp;
    if (row >= NN2) return;
    const float* h = g_H + (size_t)row * DMED;
    float a0 = 0.f, a1 = 0.f;
    for (int cb = lane; cb < DMED; cb += 32) {
        float hv = h[cb];
        a0 += hv * Wp2[cb * 2 + 0];
        a1 += hv * Wp2[cb * 2 + 1];
    }
#pragma unroll
    for (int off = 16; off; off >>= 1) {
        a0 += __shfl_down_sync(0xffffffffu, a0, off);
        a1 += __shfl_down_sync(0xffffffffu, a1, off);
    }
    if (lane == 0) {
        out[row * 2 + 0] = a0 + bp2[0];
        out[row * 2 + 1] = a1 + bp2[1];
    }
}

// ---------------- launch ----------------
extern "C" void kernel_launch(void* const* d_in, const int* in_sizes, int n_in,
                              void* d_out, int out_size)
{
    const float* lmX  = (const float*)d_in[0];
    const float* lmY  = (const float*)d_in[1];
    const float* tgX  = (const float*)d_in[2];
    // d_in[3] = tg_Y (unused by the reference output)
    const float* Wq   = (const float*)d_in[4];
    const float* bq   = (const float*)d_in[5];
    const float* Wk   = (const float*)d_in[6];
    const float* bk   = (const float*)d_in[7];
    const float* W1   = (const float*)d_in[8];
    const float* b1   = (const float*)d_in[9];
    const float* Wp1  = (const float*)d_in[10];
    const float* bp1  = (const float*)d_in[11];
    const float* Wp2  = (const float*)d_in[12];
    const float* bp2  = (const float*)d_in[13];
    const float* noise = (const float*)d_in[14];
    // d_in[15] = reserve_ratio (== 1, no effect)

    float* out  = (float*)d_out;
    float* y    = out;                                   // [3072, 2]
    float* prob = out + (size_t)NN2 * 2;                 // [6144, 6144]
    float* mask = prob + (size_t)N_TOT * N_TOT;          // [6144, 6144]

    const float invTemp = 1.0f / sqrtf(258.0f);

    qk_proj<<<dim3(KP / 32, N_TOT / 32), 256>>>(lmX, tgX, Wq, bq, invTemp, 0);
    qk_proj<<<dim3(KP / 32, N_TOT / 32), 256>>>(lmX, tgX, Wk, bk, 1.0f, 1);

    score_mma<<<dim3(N_TOT / 128, N_TOT / 128), 256>>>(noise, prob, mask);

    adj_gemm<<<dim3(NN2 / 64, KSPLIT), 256>>>(lmX);
    adj_small<<<NN2 / 8, 256>>>(lmY);
    finalf_kernel<<<NN2 / 16, 256>>>(tgX, W1, b1);
    hgemm_kernel<<<dim3(DMED / 32, NN2 / 32), 256>>>(Wp1, bp1);
    yout_kernel<<<NN2 / 8, 256>>>(Wp2, bp2, y);
}